// round 8
// baseline (speedup 1.0000x reference)
#include <cuda_runtime.h>
#include <cuda_fp16.h>
#include <cstdint>

// Problem constants: B=8192, O=64, D=64, K=64
#define BB   8192
#define OO   64
#define DD   64
#define JJN  65                 // 0 = left-linear, 1..63 cubic, 64 = right-linear
#define SLICE (JJN * 32)        // uint4 entries per d-slice = 2080 (fp16-packed, o-pairs)
#define SLICE_BYTES (SLICE * 16) // 33280
#define NDC  4                  // d-chunks (split-K)
#define DCH  (DD / NDC)         // 16
#define BT   256                // b-tile per CTA
#define NBT  (BB / BT)          // 32

typedef unsigned long long u64;

// Static device scratch
__device__ uint4 g_Ph[DD * SLICE];        // packed cubic coeffs, 2.13 MB
__device__ float g_part[NDC * BB * OO];   // split-K partials, 8 MB
__device__ unsigned g_sync_prep[NDC];     // monotonic arrival counters (32 per launch)
__device__ unsigned g_sync_done[NBT];     // monotonic arrival counters (4 per launch)

// ---------------------------------------------------------------- asm helpers
__device__ __forceinline__ u64 pk2(float a, float b) {
    u64 r; asm("mov.b64 %0, {%1, %2};" : "=l"(r) : "f"(a), "f"(b)); return r;
}
__device__ __forceinline__ float2 upk2(u64 a) {
    float2 r; asm("mov.b64 {%0, %1}, %2;" : "=f"(r.x), "=f"(r.y) : "l"(a)); return r;
}
__device__ __forceinline__ u64 add2(u64 a, u64 b) {
    u64 d; asm("add.rn.f32x2 %0, %1, %2;" : "=l"(d) : "l"(a), "l"(b)); return d;
}
__device__ __forceinline__ void mbar_init(uint32_t mbar, uint32_t cnt) {
    asm volatile("mbarrier.init.shared.b64 [%0], %1;" :: "r"(mbar), "r"(cnt) : "memory");
}
__device__ __forceinline__ void mbar_expect_tx(uint32_t mbar, uint32_t bytes) {
    asm volatile("mbarrier.arrive.expect_tx.shared::cta.b64 _, [%0], %1;"
                 :: "r"(mbar), "r"(bytes) : "memory");
}
__device__ __forceinline__ void bulk_g2s(uint32_t dst, const void* src, uint32_t bytes,
                                         uint32_t mbar) {
    asm volatile("cp.async.bulk.shared::cta.global.mbarrier::complete_tx::bytes "
                 "[%0], [%1], %2, [%3];"
                 :: "r"(dst), "l"(src), "r"(bytes), "r"(mbar) : "memory");
}
__device__ __forceinline__ void mbar_wait(uint32_t mbar, uint32_t parity) {
    asm volatile(
        "{\n"
        ".reg .pred P;\n"
        "W%=:\n"
        "mbarrier.try_wait.parity.acquire.cta.shared::cta.b64 P, [%0], %1, 0x989680;\n"
        "@P bra D%=;\n"
        "bra W%=;\n"
        "D%=:\n"
        "}"
        :: "r"(mbar), "r"(parity) : "memory");
}

// ---------------------------------------------------------------- PCHIP (exact reference math)
__device__ __forceinline__ float pchip_end(float d0, float d1) {
    float s = 0.5f * (3.0f * d0 - d1);
    if (s * d0 <= 0.0f) s = 0.0f;
    else if (d0 * d1 < 0.0f && fabsf(s) > 3.0f * fabsf(d0)) s = 3.0f * d0;
    return s;
}
__device__ __forceinline__ float pchip_mid(float dp, float dn) {
    return (dp * dn > 0.0f) ? (2.0f * dp * dn / (dp + dn + 1e-12f)) : 0.0f;
}
__device__ __forceinline__ float4 pchip_emit(int jj, float ya, float yb, float yc, float yd) {
    const float inv_h = 15.75f;     // 63/4 exact
    const float h = 4.0f / 63.0f;
    float dab = (yb - ya) * inv_h;
    float dbc = (yc - yb) * inv_h;
    float dcd = (yd - yc) * inv_h;
    float4 p;
    if (jj == 0) {
        p = make_float4(ya, h * pchip_end(dab, dbc), 0.0f, 0.0f);
    } else if (jj == 64) {
        p = make_float4(yd, h * pchip_end(dcd, dbc), 0.0f, 0.0f);
    } else {
        float y0v, y1v, m0v, m1v;
        if (jj == 1)       { y0v = ya; y1v = yb; m0v = pchip_end(dab, dbc); m1v = pchip_mid(dab, dbc); }
        else if (jj == 63) { y0v = yc; y1v = yd; m0v = pchip_mid(dbc, dcd); m1v = pchip_end(dcd, dbc); }
        else               { y0v = yb; y1v = yc; m0v = pchip_mid(dab, dbc); m1v = pchip_mid(dbc, dcd); }
        float M0 = h * m0v, M1 = h * m1v;
        p.x = y0v;
        p.y = M0;
        p.z = -3.0f * y0v + 3.0f * y1v - 2.0f * M0 - M1;
        p.w =  2.0f * y0v - 2.0f * y1v + M0 + M1;
    }
    return p;
}

// ---------------------------------------------------------------- fused kernel
// grid (NBT, NDC) = (32, 4) = 128 CTAs (one wave on 148 SMs -> spin-safe), 512 threads.
// Phase A: the 32 CTAs of group dc cooperatively build the chunk's P slices
//          (CTA bt preps d = dbase + (bt&15), jj-half = bt>>4), sync via monotonic counter.
// Phase B: bulk-DMA double-buffered contraction (identical to previous kan_main).
// Phase C: per-bt last-CTA-done reduction of the 4 split-K partials + bias -> out.
__global__ __launch_bounds__(512, 1) void kan_fused(const float* __restrict__ x,
                                                    const float* __restrict__ coeffs,
                                                    const float* __restrict__ bias,
                                                    float* __restrict__ out) {
    extern __shared__ char smraw[];
    uint4* sP = reinterpret_cast<uint4*>(smraw);                      // 2 * SLICE uint4
    float* sx = reinterpret_cast<float*>(smraw + 2 * SLICE_BYTES);    // DCH * BT floats
    uint32_t mbarBase = (uint32_t)__cvta_generic_to_shared(
        smraw + 2 * SLICE_BYTES + DCH * BT * 4);                      // 2 x 8B mbarriers
    uint32_t sb = (uint32_t)__cvta_generic_to_shared(sP);
    float* sy = reinterpret_cast<float*>(smraw);   // aliases buf0 during phase A (16.6 KB)
    __shared__ int s_last;

    const int bt = blockIdx.x, dc = blockIdx.y;
    const int tid = threadIdx.x;
    const int w = tid >> 5, lane = tid & 31;
    const int dbase = dc * DCH;
    const int b0g = bt * BT;

    // ---- Phase A1: load y-slice coeffs[:, dmy, :] (16 KB, coalesced float4)
    const int dmy  = dbase + (bt & 15);
    const int half = bt >> 4;
    for (int e = tid; e < 1024; e += 512) {
        int o = e >> 4, kk = (e & 15) << 2;
        float4 v = *reinterpret_cast<const float4*>(coeffs + (o << 12) + (dmy << 6) + kk);
        float* r = sy + o * 65 + kk;
        r[0] = v.x; r[1] = v.y; r[2] = v.z; r[3] = v.w;
    }
    __syncthreads();

    // ---- Phase A2: compute + store my jj-half of slice dmy
    {
        int lo = half ? 33 : 0;
        int hi = half ? 64 : 32;
        for (int jj = lo + w; jj <= hi; jj += 16) {
            int s = (jj == 0) ? 0 : ((jj == 64) ? 60 : min(max(jj - 2, 0), 60));
            const float* r0 = sy + lane * 65 + s;
            const float* r1 = sy + (lane + 32) * 65 + s;
            float4 pa = pchip_emit(jj, r0[0], r0[1], r0[2], r0[3]);
            float4 pb = pchip_emit(jj, r1[0], r1[1], r1[2], r1[3]);
            __half2 h0 = __floats2half2_rn(pa.x, pb.x);
            __half2 h1 = __floats2half2_rn(pa.y, pb.y);
            __half2 h2 = __floats2half2_rn(pa.z, pb.z);
            __half2 h3 = __floats2half2_rn(pa.w, pb.w);
            uint4 q;
            q.x = *reinterpret_cast<uint32_t*>(&h0);
            q.y = *reinterpret_cast<uint32_t*>(&h1);
            q.z = *reinterpret_cast<uint32_t*>(&h2);
            q.w = *reinterpret_cast<uint32_t*>(&h3);
            g_Ph[dmy * SLICE + (jj << 5) + lane] = q;
        }
    }
    __threadfence();      // release my STGs (all writer threads fence)
    __syncthreads();      // sy dead; buf0 reusable after the spin below

    unsigned my_old = 0;
    if (tid == 0) my_old = atomicAdd(&g_sync_prep[dc], 1u);

    // ---- Phase A3: x-tile load (overlaps peers' prep)  sx[dd][b_local]
    for (int e = tid; e < BT * 4; e += 512) {
        int bl = e >> 2, seg = e & 3;
        float4 v = *reinterpret_cast<const float4*>(x + (size_t)(b0g + bl) * DD + dbase + seg * 4);
        sx[(seg * 4 + 0) * BT + bl] = v.x;
        sx[(seg * 4 + 1) * BT + bl] = v.y;
        sx[(seg * 4 + 2) * BT + bl] = v.z;
        sx[(seg * 4 + 3) * BT + bl] = v.w;
    }

    // ---- Phase A4: wait for full chunk, then kick off the DMA pipeline
    if (tid == 0) {
        mbar_init(mbarBase, 1);
        mbar_init(mbarBase + 8, 1);
        unsigned target = (my_old & ~31u) + 32u;   // launches add exactly 32; monotonic
        while ((int)(*(volatile unsigned*)&g_sync_prep[dc] - target) < 0)
            __nanosleep(64);
        __threadfence();   // acquire peers' g_Ph writes before DMA reads them
        // issue first two slices
        mbar_expect_tx(mbarBase, SLICE_BYTES);
        bulk_g2s(sb, g_Ph + (size_t)dbase * SLICE, SLICE_BYTES, mbarBase);
        mbar_expect_tx(mbarBase + 8, SLICE_BYTES);
        bulk_g2s(sb + SLICE_BYTES, g_Ph + (size_t)(dbase + 1) * SLICE, SLICE_BYTES, mbarBase + 8);
    }
    __syncthreads();   // mbar init + sx visible to all

    // ---- Phase B: contraction
    u64 acc[16];
    #pragma unroll
    for (int i = 0; i < 16; i++) acc[i] = 0ULL;   // bit pattern of (0.f, 0.f)

    uint32_t ph0 = 0, ph1 = 0;

    for (int dd = 0; dd < DCH; dd++) {
        int which = dd & 1;
        if (which == 0) { mbar_wait(mbarBase, ph0);     ph0 ^= 1; }
        else            { mbar_wait(mbarBase + 8, ph1); ph1 ^= 1; }
        uint4* cur = sP + which * SLICE;

        // per-lane (jj, u) for this warp's 16 b's (lanes 16-31 mirror 0-15),
        // packed as (off << 16) | fp16(u)
        float xv = sx[dd * BT + (w << 4) + (lane & 15)];
        float t = (xv + 2.0f) * 15.75f;
        float f = fminf(fmaxf(floorf(t), 0.0f), 62.0f);
        int jj; float u;
        if (t < 0.0f)       { jj = 0;  u = t; }
        else if (t > 63.0f) { jj = 64; u = t - 63.0f; }
        else                { jj = (int)f + 1; u = t - f; }
        unsigned pk = ((unsigned)(jj << 5) << 16) |
                      (unsigned)__half_as_ushort(__float2half_rn(u));

        #pragma unroll
        for (int i = 0; i < 16; i++) {
            unsigned p   = __shfl_sync(0xffffffffu, pk, i);
            unsigned off = p >> 16;
            unsigned u2b = __byte_perm(p, p, 0x1010);     // half2(u, u)
            uint4 q = cur[off + lane];
            __half2 uu = *reinterpret_cast<__half2*>(&u2b);
            __half2 hc0 = *reinterpret_cast<__half2*>(&q.x);
            __half2 hc1 = *reinterpret_cast<__half2*>(&q.y);
            __half2 hc2 = *reinterpret_cast<__half2*>(&q.z);
            __half2 hc3 = *reinterpret_cast<__half2*>(&q.w);
            __half2 r = __hfma2(hc3, uu, hc2);
            r = __hfma2(r, uu, hc1);
            r = __hfma2(r, uu, hc0);
            float2 rf = __half22float2(r);
            acc[i] = add2(acc[i], pk2(rf.x, rf.y));
        }

        __syncthreads();   // all warps done reading buffer `which`
        if (dd + 2 < DCH && tid == 0) {
            uint32_t mb = mbarBase + (uint32_t)which * 8;
            mbar_expect_tx(mb, SLICE_BYTES);
            bulk_g2s(sb + (uint32_t)which * SLICE_BYTES,
                     g_Ph + (size_t)(dbase + dd + 2) * SLICE, SLICE_BYTES, mb);
        }
    }

    // ---- partials: part[dc][b][o]
    {
        float* pdst = g_part + ((size_t)dc * BB + b0g + (w << 4)) * OO;
        #pragma unroll
        for (int i = 0; i < 16; i++) {
            float2 v = upk2(acc[i]);
            pdst[i * OO + lane]      = v.x;
            pdst[i * OO + 32 + lane] = v.y;
        }
    }
    __threadfence();      // release partials (all writer threads)
    __syncthreads();

    // ---- Phase C: last CTA of this bt reduces the 4 chunks + bias
    if (tid == 0) {
        unsigned o2 = atomicAdd(&g_sync_done[bt], 1u);
        s_last = ((o2 & 3u) == 3u) ? 1 : 0;
    }
    __syncthreads();
    if (s_last) {
        __threadfence();   // acquire siblings' partials
        const float4* p4 = reinterpret_cast<const float4*>(g_part);
        const float4* b4 = reinterpret_cast<const float4*>(bias);
        float4* o4p = reinterpret_cast<float4*>(out);
        for (int e = tid; e < BT * 16; e += 512) {     // BT*64/4 float4
            int bl = e >> 4, o4 = e & 15;
            float4 s = b4[o4];
            #pragma unroll
            for (int c = 0; c < NDC; c++) {
                float4 v = p4[((size_t)c * BB + b0g + bl) * 16 + o4];
                s.x += v.x; s.y += v.y; s.z += v.z; s.w += v.w;
            }
            o4p[(size_t)(b0g + bl) * 16 + o4] = s;
        }
    }
}

// ---------------------------------------------------------------- launch
extern "C" void kernel_launch(void* const* d_in, const int* in_sizes, int n_in,
                              void* d_out, int out_size) {
    const float* x      = (const float*)d_in[0];   // [8192, 64]
    const float* coeffs = (const float*)d_in[1];   // [64, 64, 64]
    const float* bias   = (const float*)d_in[2];   // [64]
    float* out = (float*)d_out;                    // [8192, 64]

    const int smem = 2 * SLICE_BYTES + DCH * BT * 4 + 16;   // P bufs + sx + mbars = 82960
    cudaFuncSetAttribute(kan_fused, cudaFuncAttributeMaxDynamicSharedMemorySize, smem);

    kan_fused<<<dim3(NBT, NDC), 512, smem>>>(x, coeffs, bias, out);
}